// round 1
// baseline (speedup 1.0000x reference)
#include <cuda_runtime.h>
#include <cuda_bf16.h>

// Problem: quanvolutional layer.
// inputs:  (16, 3, 32, 32) float32
// weights: (16, 3, 16)     float32
// output:  (16, 16, 31, 31) float32  [B, O, Hp, Wp]
//
// For each output channel o (circuit type o%5), each batch b, each 2x2 patch
// (h,w): sum over input channel c of <Z0> after a 4-qubit real RY/CNOT circuit
// whose embed angles are the patch values and whose weight angles are
// weights[o,c,:].

#define HP 31
#define WP 31
#define NPOS (16 * HP * WP)   // 15376 positions (b,h,w)

// Precomputed cos/sin of half weight angles: [o][c][j] -> 2 floats
__device__ float g_wtrig[16 * 3 * 16 * 2];

__global__ void trig_kernel(const float* __restrict__ w) {
    int idx = blockIdx.x * blockDim.x + threadIdx.x;
    if (idx < 16 * 3 * 16) {
        float sn, cs;
        sincosf(0.5f * w[idx], &sn, &cs);
        g_wtrig[2 * idx]     = cs;
        g_wtrig[2 * idx + 1] = sn;
    }
}

// RY on wire W (wire 0 = MSB of 4-bit state index).
// new0 = c*a - s*b ; new1 = s*a + c*b   for pairs (i, i|bit)
template <int W>
__device__ __forceinline__ void ry(float s[16], float cs, float sn) {
    constexpr int bit = 8 >> W;
#pragma unroll
    for (int i = 0; i < 16; i++) {
        if ((i & bit) == 0) {
            float a = s[i], b = s[i | bit];
            s[i]       = cs * a - sn * b;
            s[i | bit] = sn * a + cs * b;
        }
    }
}

// CNOT control C target T: swap amplitudes where control bit set. Pure
// register renaming after full unroll (zero SASS cost).
template <int C, int T>
__device__ __forceinline__ void cx(float s[16]) {
    constexpr int cb = 8 >> C, tb = 8 >> T;
#pragma unroll
    for (int i = 0; i < 16; i++) {
        if ((i & cb) && !(i & tb)) {
            float tmp = s[i];
            s[i] = s[i | tb];
            s[i | tb] = tmp;
        }
    }
}

__global__ __launch_bounds__(256) void quanv_kernel(const float* __restrict__ in,
                                                    float* __restrict__ out) {
    const int o = blockIdx.y;  // output channel 0..15
    __shared__ float wc[3][16], ws[3][16];
    if (threadIdx.x < 48) {
        int c = threadIdx.x >> 4, j = threadIdx.x & 15;
        wc[c][j] = g_wtrig[2 * (o * 48 + threadIdx.x)];
        ws[c][j] = g_wtrig[2 * (o * 48 + threadIdx.x) + 1];
    }
    __syncthreads();

    int p = blockIdx.x * blockDim.x + threadIdx.x;
    if (p >= NPOS) return;
    int b  = p / (HP * WP);
    int hw = p - b * (HP * WP);
    int h  = hw / WP;
    int w  = hw - h * WP;

    const int circ = o % 5;
    float acc = 0.0f;

#pragma unroll 1
    for (int c = 0; c < 3; c++) {
        const float* ip = in + (((b * 3 + c) * 32) + h) * 32 + w;
        // Patch values -> embed angles (half-angle trig)
        float cs0, sn0, cs1, sn1, cs2, sn2, cs3, sn3;
        sincosf(0.5f * ip[0],  &sn0, &cs0);
        sincosf(0.5f * ip[1],  &sn1, &cs1);
        sincosf(0.5f * ip[32], &sn2, &cs2);
        sincosf(0.5f * ip[33], &sn3, &cs3);

        // Embed of |0000> with RY(x_i) on wire i is a product state.
        float s[16];
#pragma unroll
        for (int q = 0; q < 16; q++) {
            s[q] = ((q & 8) ? sn0 : cs0) * ((q & 4) ? sn1 : cs1) *
                   ((q & 2) ? sn2 : cs2) * ((q & 1) ? sn3 : cs3);
        }

        const float* WC = wc[c];
        const float* WS = ws[c];

        switch (circ) {
            case 0:  // ran
                ry<0>(s, WC[0], WS[0]); ry<1>(s, WC[1], WS[1]);
                ry<2>(s, WC[2], WS[2]); ry<3>(s, WC[3], WS[3]);
                cx<0, 1>(s); cx<2, 3>(s);
                ry<0>(s, WC[4], WS[4]); ry<2>(s, WC[5], WS[5]);
                cx<1, 2>(s);
                ry<1>(s, WC[6], WS[6]);
                break;
            case 1:  // line
                ry<0>(s, WC[0], WS[0]); ry<1>(s, WC[1], WS[1]);
                ry<2>(s, WC[2], WS[2]); ry<3>(s, WC[3], WS[3]);
                cx<0, 1>(s); cx<1, 2>(s); cx<2, 3>(s);
                ry<1>(s, WC[4], WS[4]); ry<2>(s, WC[5], WS[5]);
                ry<3>(s, WC[6], WS[6]);
                break;
            case 2:  // ring
                ry<0>(s, WC[0], WS[0]); ry<1>(s, WC[1], WS[1]);
                ry<2>(s, WC[2], WS[2]); ry<3>(s, WC[3], WS[3]);
                cx<0, 1>(s); cx<1, 2>(s); cx<2, 3>(s); cx<3, 0>(s);
                ry<0>(s, WC[4], WS[4]); ry<1>(s, WC[5], WS[5]);
                ry<2>(s, WC[6], WS[6]); ry<3>(s, WC[7], WS[7]);
                break;
            case 3:  // doublering (2 layers of 8 weights)
            {
                // layer 0
                ry<0>(s, WC[0], WS[0]); ry<1>(s, WC[1], WS[1]);
                ry<2>(s, WC[2], WS[2]); ry<3>(s, WC[3], WS[3]);
                cx<0, 1>(s); cx<1, 2>(s); cx<2, 3>(s); cx<3, 0>(s);
                ry<0>(s, WC[4], WS[4]); ry<1>(s, WC[5], WS[5]);
                ry<2>(s, WC[6], WS[6]); ry<3>(s, WC[7], WS[7]);
                cx<3, 0>(s); cx<2, 3>(s); cx<1, 2>(s); cx<0, 1>(s);
                // layer 1
                ry<0>(s, WC[8],  WS[8]);  ry<1>(s, WC[9],  WS[9]);
                ry<2>(s, WC[10], WS[10]); ry<3>(s, WC[11], WS[11]);
                cx<0, 1>(s); cx<1, 2>(s); cx<2, 3>(s); cx<3, 0>(s);
                ry<0>(s, WC[12], WS[12]); ry<1>(s, WC[13], WS[13]);
                ry<2>(s, WC[14], WS[14]); ry<3>(s, WC[15], WS[15]);
                cx<3, 0>(s); cx<2, 3>(s); cx<1, 2>(s); cx<0, 1>(s);
                break;
            }
            default:  // blockring (3 layers of 4 weights)
            {
                ry<0>(s, WC[0], WS[0]); ry<1>(s, WC[1], WS[1]);
                ry<2>(s, WC[2], WS[2]); ry<3>(s, WC[3], WS[3]);
                cx<0, 1>(s); cx<2, 3>(s); cx<1, 2>(s); cx<3, 0>(s);
                ry<0>(s, WC[4], WS[4]); ry<1>(s, WC[5], WS[5]);
                ry<2>(s, WC[6], WS[6]); ry<3>(s, WC[7], WS[7]);
                cx<0, 1>(s); cx<2, 3>(s); cx<1, 2>(s); cx<3, 0>(s);
                ry<0>(s, WC[8],  WS[8]);  ry<1>(s, WC[9],  WS[9]);
                ry<2>(s, WC[10], WS[10]); ry<3>(s, WC[11], WS[11]);
                cx<0, 1>(s); cx<2, 3>(s); cx<1, 2>(s); cx<3, 0>(s);
                break;
            }
        }

        // <Z0> = sum_{wire0=0} s^2 - sum_{wire0=1} s^2
        float e = 0.0f;
#pragma unroll
        for (int q = 0; q < 16; q++) {
            float v = s[q] * s[q];
            e = (q & 8) ? (e - v) : (e + v);
        }
        acc += e;
    }

    // out[b][o][h][w]
    out[((b * 16 + o) * HP + h) * WP + w] = acc;
}

extern "C" void kernel_launch(void* const* d_in, const int* in_sizes, int n_in,
                              void* d_out, int out_size) {
    const float* in = (const float*)d_in[0];   // (16,3,32,32)
    const float* w  = (const float*)d_in[1];   // (16,3,16)
    float* out = (float*)d_out;                // (16,16,31,31)

    trig_kernel<<<3, 256>>>(w);

    dim3 grid((NPOS + 255) / 256, 16);
    quanv_kernel<<<grid, 256>>>(in, out);
}

// round 4
// speedup vs baseline: 1.1100x; 1.1100x over previous
#include <cuda_runtime.h>
#include <cuda_bf16.h>

// Quanvolutional layer.
// inputs:  (16, 3, 32, 32) float32
// weights: (16, 3, 16)     float32
// output:  (16, 16, 31, 31) float32  [B, O, Hp, Wp]

#define HP 31
#define WP 31
#define NPOS (16 * HP * WP)   // 15376 positions (b,h,w)
#define NPIX (16 * 3 * 32 * 32)  // 49152 input pixels

// Precomputed cos/sin of half weight angles: [o][c][j] -> (cos, sin)
__device__ float g_wtrig[16 * 3 * 16 * 2];
// Precomputed per-pixel (cos(x/2), sin(x/2)), laid out like the input tensor.
__device__ float2 g_ptrig[NPIX];

__global__ void trig_kernel(const float* __restrict__ w,
                            const float* __restrict__ in) {
    int idx = blockIdx.x * blockDim.x + threadIdx.x;
    if (idx < 16 * 3 * 16) {
        float sn, cs;
        sincosf(0.5f * w[idx], &sn, &cs);
        g_wtrig[2 * idx]     = cs;
        g_wtrig[2 * idx + 1] = sn;
    }
    // Pixel trig: grid-stride so one launch covers all pixels.
    for (int p = idx; p < NPIX; p += gridDim.x * blockDim.x) {
        float sn, cs;
        sincosf(0.5f * in[p], &sn, &cs);
        g_ptrig[p] = make_float2(cs, sn);
    }
}

// RY on wire W (wire 0 = MSB of 4-bit state index).
template <int W>
__device__ __forceinline__ void ry(float s[16], float cs, float sn) {
    constexpr int bit = 8 >> W;
#pragma unroll
    for (int i = 0; i < 16; i++) {
        if ((i & bit) == 0) {
            float a = s[i], b = s[i | bit];
            s[i]       = cs * a - sn * b;
            s[i | bit] = sn * a + cs * b;
        }
    }
}

// CNOT: compile-time register permutation (zero SASS cost).
template <int C, int T>
__device__ __forceinline__ void cx(float s[16]) {
    constexpr int cb = 8 >> C, tb = 8 >> T;
#pragma unroll
    for (int i = 0; i < 16; i++) {
        if ((i & cb) && !(i & tb)) {
            float tmp = s[i];
            s[i] = s[i | tb];
            s[i | tb] = tmp;
        }
    }
}

__global__ __launch_bounds__(256) void quanv_kernel(float* __restrict__ out) {
    const int o = blockIdx.y;  // output channel 0..15
    __shared__ float wc[3][16], ws[3][16];
    if (threadIdx.x < 48) {
        int c = threadIdx.x >> 4, j = threadIdx.x & 15;
        wc[c][j] = g_wtrig[2 * (o * 48 + threadIdx.x)];
        ws[c][j] = g_wtrig[2 * (o * 48 + threadIdx.x) + 1];
    }
    __syncthreads();

    int p = blockIdx.x * blockDim.x + threadIdx.x;
    if (p >= NPOS) return;
    int b  = p / (HP * WP);
    int hw = p - b * (HP * WP);
    int h  = hw / WP;
    int w  = hw - h * WP;

    const int circ = o % 5;
    float acc = 0.0f;

#pragma unroll 1
    for (int c = 0; c < 3; c++) {
        const float2* tp = g_ptrig + (((b * 3 + c) * 32) + h) * 32 + w;
        float2 t0 = tp[0];    // pixel (h,   w)
        float2 t1 = tp[1];    // pixel (h,   w+1)
        float2 t2 = tp[32];   // pixel (h+1, w)
        float2 t3 = tp[33];   // pixel (h+1, w+1)

        // Embed product state via 2-level tree (24 muls).
        float p01[4] = { t0.x * t1.x, t0.x * t1.y, t0.y * t1.x, t0.y * t1.y };
        float p23[4] = { t2.x * t3.x, t2.x * t3.y, t2.y * t3.x, t2.y * t3.y };
        float s[16];
#pragma unroll
        for (int q = 0; q < 16; q++) s[q] = p01[q >> 2] * p23[q & 3];

        const float* WC = wc[c];
        const float* WS = ws[c];

        switch (circ) {
            case 0:  // ran
                ry<0>(s, WC[0], WS[0]); ry<1>(s, WC[1], WS[1]);
                ry<2>(s, WC[2], WS[2]); ry<3>(s, WC[3], WS[3]);
                cx<0, 1>(s); cx<2, 3>(s);
                ry<0>(s, WC[4], WS[4]); ry<2>(s, WC[5], WS[5]);
                cx<1, 2>(s);
                ry<1>(s, WC[6], WS[6]);
                break;
            case 1:  // line
                ry<0>(s, WC[0], WS[0]); ry<1>(s, WC[1], WS[1]);
                ry<2>(s, WC[2], WS[2]); ry<3>(s, WC[3], WS[3]);
                cx<0, 1>(s); cx<1, 2>(s); cx<2, 3>(s);
                ry<1>(s, WC[4], WS[4]); ry<2>(s, WC[5], WS[5]);
                ry<3>(s, WC[6], WS[6]);
                break;
            case 2:  // ring
                ry<0>(s, WC[0], WS[0]); ry<1>(s, WC[1], WS[1]);
                ry<2>(s, WC[2], WS[2]); ry<3>(s, WC[3], WS[3]);
                cx<0, 1>(s); cx<1, 2>(s); cx<2, 3>(s); cx<3, 0>(s);
                ry<0>(s, WC[4], WS[4]); ry<1>(s, WC[5], WS[5]);
                ry<2>(s, WC[6], WS[6]); ry<3>(s, WC[7], WS[7]);
                break;
            case 3:  // doublering
                ry<0>(s, WC[0], WS[0]); ry<1>(s, WC[1], WS[1]);
                ry<2>(s, WC[2], WS[2]); ry<3>(s, WC[3], WS[3]);
                cx<0, 1>(s); cx<1, 2>(s); cx<2, 3>(s); cx<3, 0>(s);
                ry<0>(s, WC[4], WS[4]); ry<1>(s, WC[5], WS[5]);
                ry<2>(s, WC[6], WS[6]); ry<3>(s, WC[7], WS[7]);
                cx<3, 0>(s); cx<2, 3>(s); cx<1, 2>(s); cx<0, 1>(s);
                ry<0>(s, WC[8],  WS[8]);  ry<1>(s, WC[9],  WS[9]);
                ry<2>(s, WC[10], WS[10]); ry<3>(s, WC[11], WS[11]);
                cx<0, 1>(s); cx<1, 2>(s); cx<2, 3>(s); cx<3, 0>(s);
                ry<0>(s, WC[12], WS[12]); ry<1>(s, WC[13], WS[13]);
                ry<2>(s, WC[14], WS[14]); ry<3>(s, WC[15], WS[15]);
                cx<3, 0>(s); cx<2, 3>(s); cx<1, 2>(s); cx<0, 1>(s);
                break;
            default:  // blockring
                ry<0>(s, WC[0], WS[0]); ry<1>(s, WC[1], WS[1]);
                ry<2>(s, WC[2], WS[2]); ry<3>(s, WC[3], WS[3]);
                cx<0, 1>(s); cx<2, 3>(s); cx<1, 2>(s); cx<3, 0>(s);
                ry<0>(s, WC[4], WS[4]); ry<1>(s, WC[5], WS[5]);
                ry<2>(s, WC[6], WS[6]); ry<3>(s, WC[7], WS[7]);
                cx<0, 1>(s); cx<2, 3>(s); cx<1, 2>(s); cx<3, 0>(s);
                ry<0>(s, WC[8],  WS[8]);  ry<1>(s, WC[9],  WS[9]);
                ry<2>(s, WC[10], WS[10]); ry<3>(s, WC[11], WS[11]);
                cx<0, 1>(s); cx<2, 3>(s); cx<1, 2>(s); cx<3, 0>(s);
                break;
        }

        // <Z0> = sum_{wire0=0} s^2 - sum_{wire0=1} s^2
        float e = 0.0f;
#pragma unroll
        for (int q = 0; q < 16; q++) {
            float v = s[q] * s[q];
            e = (q & 8) ? (e - v) : (e + v);
        }
        acc += e;
    }

    out[((b * 16 + o) * HP + h) * WP + w] = acc;
}

extern "C" void kernel_launch(void* const* d_in, const int* in_sizes, int n_in,
                              void* d_out, int out_size) {
    const float* in = (const float*)d_in[0];   // (16,3,32,32)
    const float* w  = (const float*)d_in[1];   // (16,3,16)
    float* out = (float*)d_out;                // (16,16,31,31)

    trig_kernel<<<96, 256>>>(w, in);

    dim3 grid((NPOS + 255) / 256, 16);
    quanv_kernel<<<grid, 256>>>(out);
}

// round 5
// speedup vs baseline: 1.1693x; 1.0535x over previous
#include <cuda_runtime.h>
#include <cuda_bf16.h>

// Quanvolutional layer with circuit light-cone pruning.
// inputs:  (16, 3, 32, 32) float32
// weights: (16, 3, 16)     float32
// output:  (16, 16, 31, 31) float32  [B, O, Hp, Wp]

#define HP 31
#define WP 31
#define NPOS (16 * HP * WP)      // 15376 positions (b,h,w)
#define NPIX (16 * 3 * 32 * 32)  // 49152 input pixels

// Precomputed cos/sin of half weight angles: [o][c][j] -> (cos, sin)
__device__ float g_wtrig[16 * 3 * 16 * 2];
// Precomputed per-pixel (cos(x/2), sin(x/2)), laid out like the input tensor.
__device__ float2 g_ptrig[NPIX];

__global__ void trig_kernel(const float* __restrict__ w,
                            const float* __restrict__ in) {
    int idx = blockIdx.x * blockDim.x + threadIdx.x;
    if (idx < 16 * 3 * 16) {
        float sn, cs;
        sincosf(0.5f * w[idx], &sn, &cs);
        g_wtrig[2 * idx]     = cs;
        g_wtrig[2 * idx + 1] = sn;
    }
    for (int p = idx; p < NPIX; p += gridDim.x * blockDim.x) {
        float sn, cs;
        sincosf(0.5f * in[p], &sn, &cs);
        g_ptrig[p] = make_float2(cs, sn);
    }
}

// RY on wire W (wire 0 = MSB of 4-bit state index).
template <int W>
__device__ __forceinline__ void ry(float s[16], float cs, float sn) {
    constexpr int bit = 8 >> W;
#pragma unroll
    for (int i = 0; i < 16; i++) {
        if ((i & bit) == 0) {
            float a = s[i], b = s[i | bit];
            s[i]       = cs * a - sn * b;
            s[i | bit] = sn * a + cs * b;
        }
    }
}

// CNOT: compile-time register permutation (zero SASS cost).
template <int C, int T>
__device__ __forceinline__ void cx(float s[16]) {
    constexpr int cb = 8 >> C, tb = 8 >> T;
#pragma unroll
    for (int i = 0; i < 16; i++) {
        if ((i & cb) && !(i & tb)) {
            float tmp = s[i];
            s[i] = s[i | tb];
            s[i | tb] = tmp;
        }
    }
}

// Angle addition: rotate pixel half-angle trig (cx,sx) by weight half angle.
__device__ __forceinline__ float2 fuse(float2 x, float cw, float sw) {
    return make_float2(x.x * cw - x.y * sw, x.y * cw + x.x * sw);
}

// Build product state from 4 fused wire amplitudes.
__device__ __forceinline__ void embed(float s[16], float2 a0, float2 a1,
                                      float2 a2, float2 a3) {
    float p01[4] = { a0.x * a1.x, a0.x * a1.y, a0.y * a1.x, a0.y * a1.y };
    float p23[4] = { a2.x * a3.x, a2.x * a3.y, a2.y * a3.x, a2.y * a3.y };
#pragma unroll
    for (int q = 0; q < 16; q++) s[q] = p01[q >> 2] * p23[q & 3];
}

__device__ __forceinline__ float expz0(const float s[16]) {
    float e = 0.0f;
#pragma unroll
    for (int q = 0; q < 16; q++) {
        float v = s[q] * s[q];
        e = (q & 8) ? (e - v) : (e + v);
    }
    return e;
}

__global__ __launch_bounds__(256) void quanv_kernel(float* __restrict__ out) {
    const int o = blockIdx.y;  // output channel 0..15
    __shared__ float wc[3][16], ws[3][16];
    if (threadIdx.x < 48) {
        int c = threadIdx.x >> 4, j = threadIdx.x & 15;
        wc[c][j] = g_wtrig[2 * (o * 48 + threadIdx.x)];
        ws[c][j] = g_wtrig[2 * (o * 48 + threadIdx.x) + 1];
    }
    __syncthreads();

    int p = blockIdx.x * blockDim.x + threadIdx.x;
    if (p >= NPOS) return;
    int b  = p / (HP * WP);
    int hw = p - b * (HP * WP);
    int h  = hw / WP;
    int w  = hw - h * WP;

    const int circ = o % 5;
    float acc = 0.0f;

#pragma unroll 1
    for (int c = 0; c < 3; c++) {
        const float2* tp = g_ptrig + (((b * 3 + c) * 32) + h) * 32 + w;
        const float* WC = wc[c];
        const float* WS = ws[c];

        switch (circ) {
            case 0: {  // ran -> pruned to wires {0,1}: ry0,ry1 (fused), cx01, ry0(w4)
                float2 a0 = fuse(tp[0], WC[0], WS[0]);
                float2 a1 = fuse(tp[1], WC[1], WS[1]);
                float c4 = WC[4], s4 = WS[4];
                // product amps after CNOT(0,1)
                float t00 = a0.x * a1.x, t01 = a0.x * a1.y;
                float t10 = a0.y * a1.y, t11 = a0.y * a1.x;
                // RY(w4) on wire 0: pairs (00,10),(01,11)
                float n00 = c4 * t00 - s4 * t10, n10 = s4 * t00 + c4 * t10;
                float n01 = c4 * t01 - s4 * t11, n11 = s4 * t01 + c4 * t11;
                acc += n00 * n00 + n01 * n01 - n10 * n10 - n11 * n11;
                break;
            }
            case 1: {  // line -> pruned to single qubit: <Z0> = cos(x0 + w0)
                float2 a0 = fuse(tp[0], WC[0], WS[0]);
                acc += a0.x * a0.x - a0.y * a0.y;
                break;
            }
            case 2: {  // ring -> fused embed, 4 CNOTs, ry0(w4)
                float2 a0 = fuse(tp[0],  WC[0], WS[0]);
                float2 a1 = fuse(tp[1],  WC[1], WS[1]);
                float2 a2 = fuse(tp[32], WC[2], WS[2]);
                float2 a3 = fuse(tp[33], WC[3], WS[3]);
                float s[16];
                embed(s, a0, a1, a2, a3);
                cx<0, 1>(s); cx<1, 2>(s); cx<2, 3>(s); cx<3, 0>(s);
                ry<0>(s, WC[4], WS[4]);
                acc += expz0(s);
                break;
            }
            case 3: {  // doublering -> fused embed; keep 10 RYs; prune tail
                float2 a0 = fuse(tp[0],  WC[0], WS[0]);
                float2 a1 = fuse(tp[1],  WC[1], WS[1]);
                float2 a2 = fuse(tp[32], WC[2], WS[2]);
                float2 a3 = fuse(tp[33], WC[3], WS[3]);
                float s[16];
                embed(s, a0, a1, a2, a3);
                cx<0, 1>(s); cx<1, 2>(s); cx<2, 3>(s); cx<3, 0>(s);
                ry<0>(s, WC[4], WS[4]); ry<1>(s, WC[5], WS[5]);
                ry<2>(s, WC[6], WS[6]); ry<3>(s, WC[7], WS[7]);
                cx<3, 0>(s); cx<2, 3>(s); cx<1, 2>(s); cx<0, 1>(s);
                ry<0>(s, WC[8],  WS[8]);  ry<1>(s, WC[9],  WS[9]);
                ry<2>(s, WC[10], WS[10]); ry<3>(s, WC[11], WS[11]);
                cx<0, 1>(s); cx<1, 2>(s); cx<2, 3>(s); cx<3, 0>(s);
                ry<0>(s, WC[12], WS[12]);  // ry1(w13), ry2(w14) pruned
                ry<3>(s, WC[15], WS[15]);
                cx<3, 0>(s);               // trailing cx23,cx12,cx01 pruned
                acc += expz0(s);
                break;
            }
            default: {  // blockring -> fused embed; 8 RYs remain
                float2 a0 = fuse(tp[0],  WC[0], WS[0]);
                float2 a1 = fuse(tp[1],  WC[1], WS[1]);
                float2 a2 = fuse(tp[32], WC[2], WS[2]);
                float2 a3 = fuse(tp[33], WC[3], WS[3]);
                float s[16];
                embed(s, a0, a1, a2, a3);
                cx<0, 1>(s); cx<2, 3>(s); cx<1, 2>(s); cx<3, 0>(s);
                ry<0>(s, WC[4], WS[4]); ry<1>(s, WC[5], WS[5]);
                ry<2>(s, WC[6], WS[6]); ry<3>(s, WC[7], WS[7]);
                cx<0, 1>(s); cx<2, 3>(s); cx<1, 2>(s); cx<3, 0>(s);
                ry<0>(s, WC[8],  WS[8]);  ry<1>(s, WC[9],  WS[9]);
                ry<2>(s, WC[10], WS[10]); ry<3>(s, WC[11], WS[11]);
                cx<0, 1>(s); cx<2, 3>(s); cx<1, 2>(s); cx<3, 0>(s);
                acc += expz0(s);
                break;
            }
        }
    }

    out[((b * 16 + o) * HP + h) * WP + w] = acc;
}

extern "C" void kernel_launch(void* const* d_in, const int* in_sizes, int n_in,
                              void* d_out, int out_size) {
    const float* in = (const float*)d_in[0];   // (16,3,32,32)
    const float* w  = (const float*)d_in[1];   // (16,3,16)
    float* out = (float*)d_out;                // (16,16,31,31)

    trig_kernel<<<96, 256>>>(w, in);

    dim3 grid((NPOS + 255) / 256, 16);
    quanv_kernel<<<grid, 256>>>(out);
}

// round 7
// speedup vs baseline: 1.6441x; 1.4060x over previous
#include <cuda_runtime.h>
#include <cuda_bf16.h>

// Quanvolutional layer with circuit light-cone pruning.
// inputs:  (16, 3, 32, 32) float32
// weights: (16, 3, 16)     float32
// output:  (16, 16, 31, 31) float32  [B, O, Hp, Wp]

#define HP 31
#define WP 31
#define NPOS (16 * HP * WP)      // 15376 positions (b,h,w)
#define NPIX (16 * 3 * 32 * 32)  // 49152 input pixels

// Precomputed cos/sin of half weight angles: [o][c][j] -> (cos, sin)
__device__ float2 g_wtrig[16 * 3 * 16];
// Precomputed per-pixel (cos(x/2), sin(x/2)), laid out like the input tensor.
__device__ float2 g_ptrig[NPIX];

// Heavy circuits first so the tail wave is made of cheap blocks.
// circ = o%5 cost order: 3 (doublering) > 4 (blockring) > 2 (ring) > 0 (ran) > 1 (line)
__constant__ int c_omap[16] = {3, 8, 13, 4, 9, 14, 2, 7, 12, 0, 5, 10, 15, 1, 6, 11};

__global__ __launch_bounds__(128) void trig_kernel(const float* __restrict__ w,
                                                   const float* __restrict__ in) {
    int idx = blockIdx.x * blockDim.x + threadIdx.x;  // 0..12287
    if (idx < 16 * 3 * 16) {
        float sn, cs;
        sincosf(0.5f * w[idx], &sn, &cs);
        g_wtrig[idx] = make_float2(cs, sn);
    }
    // One float4 (4 pixels) per thread; fast-path trig.
    float4 x = reinterpret_cast<const float4*>(in)[idx];
    float4 lo, hi;  // (cs0,sn0,cs1,sn1), (cs2,sn2,cs3,sn3)
    __sincosf(0.5f * x.x, &lo.y, &lo.x);
    __sincosf(0.5f * x.y, &lo.w, &lo.z);
    __sincosf(0.5f * x.z, &hi.y, &hi.x);
    __sincosf(0.5f * x.w, &hi.w, &hi.z);
    float4* outp = reinterpret_cast<float4*>(g_ptrig) + 2 * idx;
    outp[0] = lo;
    outp[1] = hi;
}

// RY on wire W (wire 0 = MSB of 4-bit state index).
template <int W>
__device__ __forceinline__ void ry(float s[16], float cs, float sn) {
    constexpr int bit = 8 >> W;
#pragma unroll
    for (int i = 0; i < 16; i++) {
        if ((i & bit) == 0) {
            float a = s[i], b = s[i | bit];
            s[i]       = cs * a - sn * b;
            s[i | bit] = sn * a + cs * b;
        }
    }
}

// CNOT: compile-time register permutation (zero SASS cost).
template <int C, int T>
__device__ __forceinline__ void cx(float s[16]) {
    constexpr int cb = 8 >> C, tb = 8 >> T;
#pragma unroll
    for (int i = 0; i < 16; i++) {
        if ((i & cb) && !(i & tb)) {
            float tmp = s[i];
            s[i] = s[i | tb];
            s[i | tb] = tmp;
        }
    }
}

// Angle addition: rotate pixel half-angle trig by weight half angle.
__device__ __forceinline__ float2 fuse(float2 x, float2 w) {
    return make_float2(x.x * w.x - x.y * w.y, x.y * w.x + x.x * w.y);
}

// Build product state from 4 fused wire amplitudes.
__device__ __forceinline__ void embed(float s[16], float2 a0, float2 a1,
                                      float2 a2, float2 a3) {
    float p01[4] = { a0.x * a1.x, a0.x * a1.y, a0.y * a1.x, a0.y * a1.y };
    float p23[4] = { a2.x * a3.x, a2.x * a3.y, a2.y * a3.x, a2.y * a3.y };
#pragma unroll
    for (int q = 0; q < 16; q++) s[q] = p01[q >> 2] * p23[q & 3];
}

__device__ __forceinline__ float expz0(const float s[16]) {
    float e = 0.0f;
#pragma unroll
    for (int q = 0; q < 16; q++) {
        float v = s[q] * s[q];
        e = (q & 8) ? (e - v) : (e + v);
    }
    return e;
}

__global__ __launch_bounds__(128) void quanv_kernel(float* __restrict__ out) {
    const int o = c_omap[blockIdx.y];  // output channel, heavy circuits first
    __shared__ float2 wcs[3][16];
    if (threadIdx.x < 48) {
        int c = threadIdx.x >> 4, j = threadIdx.x & 15;
        wcs[c][j] = g_wtrig[o * 48 + threadIdx.x];
    }
    __syncthreads();

    int p = blockIdx.x * blockDim.x + threadIdx.x;
    if (p >= NPOS) return;
    int b  = p / (HP * WP);
    int hw = p - b * (HP * WP);
    int h  = hw / WP;
    int w  = hw - h * WP;

    const int circ = o % 5;
    float acc = 0.0f;

#pragma unroll 1
    for (int c = 0; c < 3; c++) {
        const float2* tp = g_ptrig + (((b * 3 + c) * 32) + h) * 32 + w;
        const float2* W = wcs[c];

        switch (circ) {
            case 0: {  // ran -> pruned to wires {0,1}: ry0,ry1 (fused), cx01, ry0(w4)
                float2 a0 = fuse(tp[0], W[0]);
                float2 a1 = fuse(tp[1], W[1]);
                float c4 = W[4].x, s4 = W[4].y;
                // product amps after CNOT(0,1)
                float t00 = a0.x * a1.x, t01 = a0.x * a1.y;
                float t10 = a0.y * a1.y, t11 = a0.y * a1.x;
                // RY(w4) on wire 0: pairs (00,10),(01,11)
                float n00 = c4 * t00 - s4 * t10, n10 = s4 * t00 + c4 * t10;
                float n01 = c4 * t01 - s4 * t11, n11 = s4 * t01 + c4 * t11;
                acc += n00 * n00 + n01 * n01 - n10 * n10 - n11 * n11;
                break;
            }
            case 1: {  // line -> pruned to single qubit: <Z0> = cos(x0 + w0)
                float2 a0 = fuse(tp[0], W[0]);
                acc += a0.x * a0.x - a0.y * a0.y;
                break;
            }
            case 2: {  // ring -> fused embed, 4 CNOTs, ry0(w4)
                float s[16];
                embed(s, fuse(tp[0], W[0]), fuse(tp[1], W[1]),
                         fuse(tp[32], W[2]), fuse(tp[33], W[3]));
                cx<0, 1>(s); cx<1, 2>(s); cx<2, 3>(s); cx<3, 0>(s);
                ry<0>(s, W[4].x, W[4].y);
                acc += expz0(s);
                break;
            }
            case 3: {  // doublering -> fused embed; 10 RYs; pruned tail
                float s[16];
                embed(s, fuse(tp[0], W[0]), fuse(tp[1], W[1]),
                         fuse(tp[32], W[2]), fuse(tp[33], W[3]));
                cx<0, 1>(s); cx<1, 2>(s); cx<2, 3>(s); cx<3, 0>(s);
                ry<0>(s, W[4].x, W[4].y); ry<1>(s, W[5].x, W[5].y);
                ry<2>(s, W[6].x, W[6].y); ry<3>(s, W[7].x, W[7].y);
                cx<3, 0>(s); cx<2, 3>(s); cx<1, 2>(s); cx<0, 1>(s);
                ry<0>(s, W[8].x,  W[8].y);  ry<1>(s, W[9].x,  W[9].y);
                ry<2>(s, W[10].x, W[10].y); ry<3>(s, W[11].x, W[11].y);
                cx<0, 1>(s); cx<1, 2>(s); cx<2, 3>(s); cx<3, 0>(s);
                ry<0>(s, W[12].x, W[12].y);  // ry1(w13), ry2(w14) pruned
                ry<3>(s, W[15].x, W[15].y);
                cx<3, 0>(s);                 // trailing cx23,cx12,cx01 pruned
                acc += expz0(s);
                break;
            }
            default: {  // blockring -> fused embed; 8 RYs remain
                float s[16];
                embed(s, fuse(tp[0], W[0]), fuse(tp[1], W[1]),
                         fuse(tp[32], W[2]), fuse(tp[33], W[3]));
                cx<0, 1>(s); cx<2, 3>(s); cx<1, 2>(s); cx<3, 0>(s);
                ry<0>(s, W[4].x, W[4].y); ry<1>(s, W[5].x, W[5].y);
                ry<2>(s, W[6].x, W[6].y); ry<3>(s, W[7].x, W[7].y);
                cx<0, 1>(s); cx<2, 3>(s); cx<1, 2>(s); cx<3, 0>(s);
                ry<0>(s, W[8].x,  W[8].y);  ry<1>(s, W[9].x,  W[9].y);
                ry<2>(s, W[10].x, W[10].y); ry<3>(s, W[11].x, W[11].y);
                cx<0, 1>(s); cx<2, 3>(s); cx<1, 2>(s); cx<3, 0>(s);
                acc += expz0(s);
                break;
            }
        }
    }

    out[((b * 16 + o) * HP + h) * WP + w] = acc;
}

extern "C" void kernel_launch(void* const* d_in, const int* in_sizes, int n_in,
                              void* d_out, int out_size) {
    const float* in = (const float*)d_in[0];   // (16,3,32,32)
    const float* w  = (const float*)d_in[1];   // (16,3,16)
    float* out = (float*)d_out;                // (16,16,31,31)

    trig_kernel<<<96, 128>>>(w, in);           // 12288 threads = NPIX/4

    dim3 grid((NPOS + 127) / 128, 16);
    quanv_kernel<<<grid, 128>>>(out);
}